// round 1
// baseline (speedup 1.0000x reference)
#include <cuda_runtime.h>

// Problem constants
#define B_     4
#define C_IN_  32
#define C_OUT_ 64
#define E_     200000
#define KK_    5
#define CKDIM  (C_IN_ * KK_)   // 160
#define TILE_E 64
#define NTHREADS 256

// Transposed x scratch: (B, E, C) so each edge's 32-channel feature is one
// contiguous 128B line (gather-friendly). Static device array — no allocation.
__device__ float g_xT[(size_t)B_ * E_ * C_IN_];

// ---------------------------------------------------------------------------
// Kernel 1: transpose x (B, C, E) -> g_xT (B, E, C). 32x32 smem tile.
// E = 200000 is divisible by 32, C_IN = 32 exactly -> no tails.
// ---------------------------------------------------------------------------
__global__ void __launch_bounds__(1024) transpose_kernel(const float* __restrict__ x) {
    __shared__ float tile[32][33];
    const int b  = blockIdx.y;
    const int e0 = blockIdx.x * 32;
    const int tx = threadIdx.x;
    const int ty = threadIdx.y;
    // coalesced read along E: x[b][ty][e0+tx]
    tile[ty][tx] = x[((size_t)b * C_IN_ + ty) * E_ + (e0 + tx)];
    __syncthreads();
    // coalesced write along C: xT[b][e0+ty][tx]
    g_xT[((size_t)b * E_ + (e0 + ty)) * C_IN_ + tx] = tile[tx][ty];
}

// ---------------------------------------------------------------------------
// Kernel 2: fused gather + symmetric combine + GEMM.
// Block: 256 threads, one batch b, 64 edges, all 64 output channels.
//   Phase 1: build sG[ck][e]  (ck = c*5 + tap, 160 x 64)
//   Phase 2: 64x64 output tile, 4x4 register tile/thread, K=160 reduction.
// Smem: sW (40KB) + sG (40KB) = 80KB dynamic -> 2 blocks/SM.
// ---------------------------------------------------------------------------
__global__ void __launch_bounds__(NTHREADS, 2)
meshconv_kernel(const int*   __restrict__ Gi,
                const float* __restrict__ W,
                const float* __restrict__ bias,
                float*       __restrict__ out) {
    extern __shared__ float smem[];
    float* sW = smem;                     // [160 * 64], sW[ck*64 + o]
    float* sG = smem + CKDIM * TILE_E;    // [160 * 64], sG[ck*64 + e]

    const int t      = threadIdx.x;
    const int b      = blockIdx.y;
    const int e_base = blockIdx.x * TILE_E;

    // --- cooperative W load: sW[ck*64 + o] = W[o*160 + ck] (W stays L2-hot) ---
    #pragma unroll 4
    for (int i = t; i < CKDIM * C_OUT_; i += NTHREADS) {
        int ck = i >> 6;
        int o  = i & 63;
        sW[i] = W[o * CKDIM + ck];
    }

    // --- Phase 1: gather + combine ------------------------------------------
    // Thread mapping: cg = t/64 (channel group, 8 channels), el = t%64 (edge).
    // Within a warp cg is constant and el is lane-contiguous -> STS conflict-free.
    {
        const int cg = t >> 6;     // 0..3
        const int el = t & 63;     // 0..63
        const int e  = e_base + el;

        const int* gi = Gi + ((size_t)b * E_ + e) * KK_;
        int idx[KK_];
        #pragma unroll
        for (int j = 0; j < KK_; j++) idx[j] = gi[j];

        const float* xb = g_xT + (size_t)b * E_ * C_IN_ + cg * 8;
        float4 fa[KK_], fb[KK_];
        #pragma unroll
        for (int j = 0; j < KK_; j++) {
            const float4* p = (const float4*)(xb + (size_t)idx[j] * C_IN_);
            fa[j] = p[0];          // channels cg*8 + 0..3
            fb[j] = p[1];          // channels cg*8 + 4..7
        }

        float f[KK_][8];
        #pragma unroll
        for (int j = 0; j < KK_; j++) {
            f[j][0] = fa[j].x; f[j][1] = fa[j].y; f[j][2] = fa[j].z; f[j][3] = fa[j].w;
            f[j][4] = fb[j].x; f[j][5] = fb[j].y; f[j][6] = fb[j].z; f[j][7] = fb[j].w;
        }

        #pragma unroll
        for (int ci = 0; ci < 8; ci++) {
            const int c = cg * 8 + ci;
            const float f0 = f[0][ci], f1 = f[1][ci], f2 = f[2][ci],
                        f3 = f[3][ci], f4 = f[4][ci];
            float* dst = sG + (c * KK_) * TILE_E + el;
            dst[0 * TILE_E] = f0;
            dst[1 * TILE_E] = f1 + f3;
            dst[2 * TILE_E] = f2 + f4;
            dst[3 * TILE_E] = fabsf(f1 - f3);
            dst[4 * TILE_E] = fabsf(f2 - f4);
        }
    }
    __syncthreads();

    // --- Phase 2: GEMM 64(out) x 64(edge) x 160(ck) -------------------------
    const int o_t = (t >> 4) << 2;   // 0,4,...,60
    const int e_t = (t & 15) << 2;   // 0,4,...,60

    float acc[4][4] = {{0.f}};
    const float4* pW = (const float4*)(sW + o_t);   // step 16 float4 per k
    const float4* pG = (const float4*)(sG + e_t);

    #pragma unroll 8
    for (int k = 0; k < CKDIM; k++) {
        const float4 w = pW[k * (TILE_E / 4)];
        const float4 g = pG[k * (TILE_E / 4)];
        acc[0][0] += w.x * g.x; acc[0][1] += w.x * g.y;
        acc[0][2] += w.x * g.z; acc[0][3] += w.x * g.w;
        acc[1][0] += w.y * g.x; acc[1][1] += w.y * g.y;
        acc[1][2] += w.y * g.z; acc[1][3] += w.y * g.w;
        acc[2][0] += w.z * g.x; acc[2][1] += w.z * g.y;
        acc[2][2] += w.z * g.z; acc[2][3] += w.z * g.w;
        acc[3][0] += w.w * g.x; acc[3][1] += w.w * g.y;
        acc[3][2] += w.w * g.z; acc[3][3] += w.w * g.w;
    }

    // --- epilogue: add bias, coalesced float4 stores ------------------------
    #pragma unroll
    for (int i = 0; i < 4; i++) {
        const float bo = bias[o_t + i];
        float4 v = make_float4(acc[i][0] + bo, acc[i][1] + bo,
                               acc[i][2] + bo, acc[i][3] + bo);
        *(float4*)&out[((size_t)b * C_OUT_ + o_t + i) * E_ + e_base + e_t] = v;
    }
}

// ---------------------------------------------------------------------------
extern "C" void kernel_launch(void* const* d_in, const int* in_sizes, int n_in,
                              void* d_out, int out_size) {
    const float* x    = (const float*)d_in[0];   // (4, 32, 200000) fp32
    const int*   Gi   = (const int*)  d_in[1];   // (4, 200000, 5) int32
    const float* W    = (const float*)d_in[2];   // (64, 32, 1, 5) fp32
    const float* bias = (const float*)d_in[3];   // (64,) fp32
    float*       out  = (float*)d_out;           // (4, 64, 200000, 1) fp32

    // Kernel 1: transpose x -> (B, E, C)
    dim3 tb(32, 32);
    dim3 tg(E_ / 32, B_);
    transpose_kernel<<<tg, tb>>>(x);

    // Kernel 2: fused gather + combine + GEMM
    const int smem_bytes = 2 * CKDIM * TILE_E * (int)sizeof(float);  // 81920
    cudaFuncSetAttribute(meshconv_kernel,
                         cudaFuncAttributeMaxDynamicSharedMemorySize, smem_bytes);
    dim3 g2(E_ / TILE_E, B_);
    meshconv_kernel<<<g2, NTHREADS, smem_bytes>>>(Gi, W, bias, out);
}

// round 2
// speedup vs baseline: 2.2968x; 2.2968x over previous
#include <cuda_runtime.h>

// Problem constants
#define B_      4
#define C_IN_   32
#define C_OUT_  64
#define E_      200000
#define KK_     5
#define CKDIM   160            // C_IN * K
#define TILE_E  64
#define NLINES  (TILE_E * KK_) // 320 gathered lines per block

// Global scratch (static __device__ arrays: allocation-guard safe)
__device__ __align__(128) float g_xT[(size_t)B_ * E_ * C_IN_];   // (B, E, C)
__device__ __align__(128) float g_Wt[CKDIM * C_OUT_];            // [ck][o]

// ---------------------------------------------------------------------------
// Kernel 1: transpose x (B, C, E) -> g_xT (B, E, C). 32x32 tile, 256 threads.
// ---------------------------------------------------------------------------
__global__ void __launch_bounds__(256) transpose_x(const float* __restrict__ x) {
    __shared__ float tile[32][33];
    const int b  = blockIdx.y;
    const int e0 = blockIdx.x * 32;
    const int tx = threadIdx.x & 31;
    const int ty = threadIdx.x >> 5;   // 0..7
    #pragma unroll
    for (int i = 0; i < 4; i++) {
        const int c = ty + i * 8;
        tile[c][tx] = x[((size_t)b * C_IN_ + c) * E_ + e0 + tx];  // coalesced over E
    }
    __syncthreads();
    #pragma unroll
    for (int i = 0; i < 4; i++) {
        const int e = ty + i * 8;
        g_xT[((size_t)b * E_ + e0 + e) * C_IN_ + tx] = tile[tx][e];  // coalesced over C
    }
}

// ---------------------------------------------------------------------------
// Kernel 2: transpose W (64, 160) -> g_Wt (160, 64). One block, runs in ~2us.
// ---------------------------------------------------------------------------
__global__ void __launch_bounds__(256) transpose_W(const float* __restrict__ W) {
    __shared__ float tile[64][33];
    const int t  = threadIdx.x;
    const int tx = t & 31;
    const int ty = t >> 5;
    for (int kc = 0; kc < 5; kc++) {
        __syncthreads();
        #pragma unroll
        for (int i = 0; i < 8; i++) {
            const int o = ty + i * 8;
            tile[o][tx] = W[o * CKDIM + kc * 32 + tx];   // coalesced read
        }
        __syncthreads();
        const int o  = t & 63;
        const int kq = t >> 6;
        #pragma unroll
        for (int r = 0; r < 8; r++) {
            const int kl = kq * 8 + r;
            g_Wt[(kc * 32 + kl) * C_OUT_ + o] = tile[o][kl];  // coalesced write
        }
    }
}

// ---------------------------------------------------------------------------
// Kernel 3: fused gather + combine + GEMM.
//   128 threads, tile = 64 out x 64 edges, micro-tile 8o x 4e (32 acc).
//   smem: sW[160][64] (40KB) + sG buffer (40KB, first used as raw line staging,
//   then rewritten in-place with combined G in [ck][e] layout).
//   80KB dynamic -> 2 blocks/SM for cross-block phase overlap.
// ---------------------------------------------------------------------------
__global__ void __launch_bounds__(128, 2)
meshconv_kernel(const int*   __restrict__ Gi,
                const float* __restrict__ bias,
                float*       __restrict__ out) {
    extern __shared__ float smem[];
    float* sW = smem;                     // [160*64] : sW[k*64 + o]
    float* sG = smem + CKDIM * TILE_E;    // raw staging, then sG[k*64 + e]

    const int t      = threadIdx.x;
    const int w      = t >> 5;            // warp 0..3
    const int l      = t & 31;            // lane
    const int b      = blockIdx.y;
    const int e_base = blockIdx.x * TILE_E;

    // ---- Phase 0a: issue Gi loads (long latency, start early) --------------
    // Cooperative gather: lane sub-group of 8 handles one 128B line.
    const int sub = l >> 3;               // 0..3 : which line in this instr
    const int seg = l & 7;                // 0..7 : 16B segment within line
    const int* GiB = Gi + ((size_t)b * E_ + e_base) * KK_;  // flat (e_loc*5+j)

    int lineIdx[20];
    #pragma unroll
    for (int i = 0; i < 20; i++) {
        const int line = w * 4 + sub + i * 16;   // 0..319
        lineIdx[i] = GiB[line];                  // 4 distinct ints, 8-lane bcast
    }

    // ---- Phase 0b: W load, coalesced copy from pre-transposed g_Wt ---------
    #pragma unroll
    for (int i = 0; i < 20; i++) {
        ((float4*)sW)[t + i * 128] = ((const float4*)g_Wt)[t + i * 128];
    }

    // ---- Phase 0c: gather x lines (4 random 128B lines per LDG.128) --------
    const float* xb = g_xT + (size_t)b * E_ * C_IN_;
    float4 v[20];
    #pragma unroll
    for (int i = 0; i < 20; i++) {
        v[i] = *(const float4*)(xb + (size_t)lineIdx[i] * C_IN_ + seg * 4);
    }
    // STS raw lines with per-row XOR swizzle (bank-balanced both directions)
    #pragma unroll
    for (int i = 0; i < 20; i++) {
        const int line  = w * 4 + sub + i * 16;
        const int chunk = seg ^ (line & 7);
        ((float4*)sG)[line * 8 + chunk] = v[i];
    }
    __syncthreads();

    // ---- Phase 1: combine (in-place: read-all -> sync -> write-all) --------
    {
        const int e_loc = t & 63;         // 32 distinct edges per warp
        const int chh   = t >> 6;         // 0/1 : channels chh*16 .. +15
        float f[KK_][16];
        #pragma unroll
        for (int j = 0; j < KK_; j++) {
            const int row = e_loc * KK_ + j;
            #pragma unroll
            for (int q = 0; q < 4; q++) {
                const int chunk = (chh * 4 + q) ^ (row & 7);
                const float4 tmp = ((const float4*)sG)[row * 8 + chunk];
                f[j][q * 4 + 0] = tmp.x;
                f[j][q * 4 + 1] = tmp.y;
                f[j][q * 4 + 2] = tmp.z;
                f[j][q * 4 + 3] = tmp.w;
            }
        }
        __syncthreads();   // all raw reads complete before overwriting buffer
        #pragma unroll
        for (int ci = 0; ci < 16; ci++) {
            const int c = chh * 16 + ci;
            const float f0 = f[0][ci], f1 = f[1][ci], f2 = f[2][ci],
                        f3 = f[3][ci], f4 = f[4][ci];
            float* dst = sG + (c * KK_) * TILE_E + e_loc;  // conflict-free STS
            dst[0 * TILE_E] = f0;
            dst[1 * TILE_E] = f1 + f3;
            dst[2 * TILE_E] = f2 + f4;
            dst[3 * TILE_E] = fabsf(f1 - f3);
            dst[4 * TILE_E] = fabsf(f2 - f4);
        }
    }
    __syncthreads();

    // ---- Phase 2: GEMM 64o x 64e x 160k, micro 8o x 4e ---------------------
    const int og = t >> 4;       // 0..7
    const int eg = t & 15;       // 0..15
    const int o0 = og * 4;       // low 4 outputs; high 4 at o0+32

    float acc[8][4] = {{0.f}};
    #pragma unroll 8
    for (int k = 0; k < CKDIM; k++) {
        const float4 wl = *(const float4*)(sW + k * 64 + o0);        // broadcast
        const float4 wh = *(const float4*)(sW + k * 64 + o0 + 32);   // broadcast
        const float4 g  = *(const float4*)(sG + k * 64 + eg * 4);    // 256B/warp
        acc[0][0] += wl.x * g.x; acc[0][1] += wl.x * g.y; acc[0][2] += wl.x * g.z; acc[0][3] += wl.x * g.w;
        acc[1][0] += wl.y * g.x; acc[1][1] += wl.y * g.y; acc[1][2] += wl.y * g.z; acc[1][3] += wl.y * g.w;
        acc[2][0] += wl.z * g.x; acc[2][1] += wl.z * g.y; acc[2][2] += wl.z * g.z; acc[2][3] += wl.z * g.w;
        acc[3][0] += wl.w * g.x; acc[3][1] += wl.w * g.y; acc[3][2] += wl.w * g.z; acc[3][3] += wl.w * g.w;
        acc[4][0] += wh.x * g.x; acc[4][1] += wh.x * g.y; acc[4][2] += wh.x * g.z; acc[4][3] += wh.x * g.w;
        acc[5][0] += wh.y * g.x; acc[5][1] += wh.y * g.y; acc[5][2] += wh.y * g.z; acc[5][3] += wh.y * g.w;
        acc[6][0] += wh.z * g.x; acc[6][1] += wh.z * g.y; acc[6][2] += wh.z * g.z; acc[6][3] += wh.z * g.w;
        acc[7][0] += wh.w * g.x; acc[7][1] += wh.w * g.y; acc[7][2] += wh.w * g.z; acc[7][3] += wh.w * g.w;
    }

    // ---- Epilogue: bias + coalesced float4 stores --------------------------
    #pragma unroll
    for (int i = 0; i < 8; i++) {
        const int o  = (i < 4) ? (o0 + i) : (o0 + 32 + (i - 4));
        const float bo = __ldg(&bias[o]);
        float4 r = make_float4(acc[i][0] + bo, acc[i][1] + bo,
                               acc[i][2] + bo, acc[i][3] + bo);
        *(float4*)(out + ((size_t)(b * C_OUT_ + o)) * E_ + e_base + eg * 4) = r;
    }
}

// ---------------------------------------------------------------------------
extern "C" void kernel_launch(void* const* d_in, const int* in_sizes, int n_in,
                              void* d_out, int out_size) {
    const float* x    = (const float*)d_in[0];   // (4, 32, 200000) fp32
    const int*   Gi   = (const int*)  d_in[1];   // (4, 200000, 5) int32
    const float* W    = (const float*)d_in[2];   // (64, 32, 1, 5) fp32
    const float* bias = (const float*)d_in[3];   // (64,) fp32
    float*       out  = (float*)d_out;           // (4, 64, 200000, 1) fp32

    transpose_x<<<dim3(E_ / 32, B_), 256>>>(x);
    transpose_W<<<1, 256>>>(W);

    const int smem_bytes = 2 * CKDIM * TILE_E * (int)sizeof(float);  // 81920
    cudaFuncSetAttribute(meshconv_kernel,
                         cudaFuncAttributeMaxDynamicSharedMemorySize, smem_bytes);
    meshconv_kernel<<<dim3(E_ / TILE_E, B_), 128, smem_bytes>>>(Gi, bias, out);
}

// round 5
// speedup vs baseline: 2.8515x; 1.2415x over previous
#include <cuda_runtime.h>
#include <cuda_bf16.h>
#include <cstdint>

// Problem constants
#define B_      4
#define C_IN_   32
#define C_OUT_  64
#define E_      200000
#define KK_     5
#define CKDIM   160
#define TILE_M  128            // edges per tile
#define NTHR    512
#define NCH     20             // 16B chunks per row (160 bf16 k-values)

#define N_TILES ((E_ + TILE_M - 1) / TILE_M)   // 1563

// SMEM byte offsets
#define SM_BHI   0             // 64 x 320B = 20480
#define SM_BLO   20480         // 20480
#define SM_A     40960         // Ahi 40960 | Alo 40960  (raw staging overlays both)
#define SM_ALO_R 40960         // Alo offset relative to SM_A base region
#define SM_RAW   40960         // 640 lines x 128B = 81920 (overlays A panels)
#define SM_TOTAL 122880

// Global scratch
__device__ __align__(128) float g_xT[(size_t)B_ * E_ * C_IN_];   // (B,E,C)
__device__ __align__(128) unsigned char g_Bsplit[40960];         // Bhi | Blo panels

// ---------------------------------------------------------------------------
// helpers
// ---------------------------------------------------------------------------
__device__ __forceinline__ uint32_t smem_u32(const void* p) {
    uint32_t a;
    asm("{ .reg .u64 t; cvta.to.shared.u64 t, %1; cvt.u32.u64 %0, t; }" : "=r"(a) : "l"(p));
    return a;
}
// chunk swizzle: rows have 20 chunks of 16B; XOR keeps range within [0,20)
__device__ __forceinline__ int swzc(int kc, int row) {
    return (kc < 16) ? (kc ^ (row & 7)) : (16 + ((kc - 16) ^ (row & 3)));
}
__device__ __forceinline__ void ldm_x4(uint32_t* r, uint32_t addr) {
    asm volatile("ldmatrix.sync.aligned.m8n8.x4.shared.b16 {%0,%1,%2,%3}, [%4];"
        : "=r"(r[0]), "=r"(r[1]), "=r"(r[2]), "=r"(r[3]) : "r"(addr));
}
__device__ __forceinline__ void mma16816(float* d, const uint32_t* a, const uint32_t* b) {
    asm volatile(
        "mma.sync.aligned.m16n8k16.row.col.f32.bf16.bf16.f32 "
        "{%0,%1,%2,%3}, {%4,%5,%6,%7}, {%8,%9}, {%0,%1,%2,%3};"
        : "+f"(d[0]), "+f"(d[1]), "+f"(d[2]), "+f"(d[3])
        : "r"(a[0]), "r"(a[1]), "r"(a[2]), "r"(a[3]), "r"(b[0]), "r"(b[1]));
}
__device__ __forceinline__ uint32_t pack_bf16(__nv_bfloat16 a, __nv_bfloat16 b) {
    __nv_bfloat162 h2 = __halves2bfloat162(a, b);
    return *reinterpret_cast<uint32_t*>(&h2);
}

// ---------------------------------------------------------------------------
// Kernel 1: transpose x (B,C,E) -> g_xT (B,E,C)
// ---------------------------------------------------------------------------
__global__ void __launch_bounds__(256) transpose_x(const float* __restrict__ x) {
    __shared__ float tile[32][33];
    const int b  = blockIdx.y;
    const int e0 = blockIdx.x * 32;
    const int tx = threadIdx.x & 31;
    const int ty = threadIdx.x >> 5;
    #pragma unroll
    for (int i = 0; i < 4; i++) {
        const int c = ty + i * 8;
        tile[c][tx] = x[((size_t)b * C_IN_ + c) * E_ + e0 + tx];
    }
    __syncthreads();
    #pragma unroll
    for (int i = 0; i < 4; i++) {
        const int e = ty + i * 8;
        g_xT[((size_t)b * E_ + e0 + e) * C_IN_ + tx] = tile[tx][e];
    }
}

// ---------------------------------------------------------------------------
// Kernel 2: split W into bf16 hi/lo, remap k = j*32 + c, swizzled chunk layout
// ---------------------------------------------------------------------------
__global__ void __launch_bounds__(512) prep_W(const float* __restrict__ W) {
    for (int i = threadIdx.x; i < C_OUT_ * CKDIM; i += 512) {
        const int o   = i / CKDIM;
        const int rem = i - o * CKDIM;
        const int c   = rem / KK_;
        const int j   = rem - c * KK_;
        const int k   = j * 32 + c;
        const int kc  = k >> 3;
        const int ki  = k & 7;
        const float v = W[i];
        const __nv_bfloat16 hi = __float2bfloat16_rn(v);
        const __nv_bfloat16 lo = __float2bfloat16_rn(v - __bfloat162float(hi));
        const uint32_t off = (uint32_t)((o * NCH + swzc(kc, o)) * 16 + ki * 2);
        *reinterpret_cast<__nv_bfloat16*>(g_Bsplit + off)         = hi;
        *reinterpret_cast<__nv_bfloat16*>(g_Bsplit + 20480 + off) = lo;
    }
}

// ---------------------------------------------------------------------------
// Kernel 3: fused gather + combine + split + HMMA GEMM + epilogue.
//   512 threads, 1 CTA/SM, 16 warps each own a 16m x 32n fragment tile.
// ---------------------------------------------------------------------------
__global__ void __launch_bounds__(NTHR, 1)
meshconv_kernel(const int*   __restrict__ Gi,
                const float* __restrict__ bias,
                float*       __restrict__ out) {
    extern __shared__ __align__(1024) unsigned char smem[];
    const uint32_t sbase = smem_u32(smem);

    const int t      = threadIdx.x;
    const int w      = t >> 5;
    const int l      = t & 31;
    const int b      = blockIdx.y;
    const int e_base = blockIdx.x * TILE_M;

    // --- Gi loads (start early; 8-lane groups share one 128B line) ----------
    const int sub = l >> 3;               // 0..3
    const int seg = l & 7;                // 0..7 (16B segment in line)
    const int* GiB = Gi + (size_t)b * E_ * KK_ + (size_t)e_base * KK_;
    const int valid = (E_ - e_base) * KK_;            // <= 640
    int lineIdx[10];
    #pragma unroll
    for (int i = 0; i < 10; i++) {
        const int line = (w * 4 + sub) + i * 64;      // 0..639
        lineIdx[i] = (line < valid) ? GiB[line] : 0;
    }

    // --- B panels: coalesced copy of pre-split Bhi|Blo (40KB) ---------------
    {
        const uint4* src = (const uint4*)g_Bsplit;
        uint4* dst = (uint4*)smem;
        #pragma unroll
        for (int i = 0; i < 5; i++) dst[t + i * NTHR] = src[t + i * NTHR];
    }

    // --- gather x lines into raw staging (overlays A panels) ----------------
    const float* xb = g_xT + (size_t)b * E_ * C_IN_;
    float4 v[10];
    #pragma unroll
    for (int i = 0; i < 10; i++) {
        v[i] = *(const float4*)(xb + (size_t)lineIdx[i] * C_IN_ + seg * 4);
    }
    float4* sRaw4 = (float4*)(smem + SM_RAW);
    #pragma unroll
    for (int i = 0; i < 10; i++) {
        const int line  = (w * 4 + sub) + i * 64;
        const int chunk = seg ^ (line & 7);
        sRaw4[line * 8 + chunk] = v[i];
    }
    __syncthreads();

    // --- combine + bf16 hi/lo split; read raw -> regs, sync, write panels ---
    {
        const int e_loc = t >> 2;          // 0..127
        const int quad  = t & 3;           // channels quad*8 .. quad*8+7
        float f[KK_][8];
        #pragma unroll
        for (int j = 0; j < KK_; j++) {
            const int row = e_loc * KK_ + j;
            #pragma unroll
            for (int q = 0; q < 2; q++) {
                const int chunk = (quad * 2 + q) ^ (row & 7);
                const float4 tmp = sRaw4[row * 8 + chunk];
                f[j][q * 4 + 0] = tmp.x; f[j][q * 4 + 1] = tmp.y;
                f[j][q * 4 + 2] = tmp.z; f[j][q * 4 + 3] = tmp.w;
            }
        }
        __syncthreads();   // raw fully consumed; safe to overwrite with panels

        #pragma unroll
        for (int j = 0; j < KK_; j++) {
            float g[8];
            #pragma unroll
            for (int ci = 0; ci < 8; ci++) {
                const float f0 = f[0][ci], f1 = f[1][ci], f2 = f[2][ci],
                            f3 = f[3][ci], f4 = f[4][ci];
                switch (j) {
                    case 0: g[ci] = f0; break;
                    case 1: g[ci] = f1 + f3; break;
                    case 2: g[ci] = f2 + f4; break;
                    case 3: g[ci] = fabsf(f1 - f3); break;
                    default: g[ci] = fabsf(f2 - f4); break;
                }
            }
            uint4 hi4, lo4;
            uint32_t* hp = (uint32_t*)&hi4;
            uint32_t* lp = (uint32_t*)&lo4;
            #pragma unroll
            for (int p = 0; p < 4; p++) {
                const __nv_bfloat16 h0 = __float2bfloat16_rn(g[2 * p]);
                const __nv_bfloat16 h1 = __float2bfloat16_rn(g[2 * p + 1]);
                const __nv_bfloat16 l0 = __float2bfloat16_rn(g[2 * p] - __bfloat162float(h0));
                const __nv_bfloat16 l1 = __float2bfloat16_rn(g[2 * p + 1] - __bfloat162float(h1));
                hp[p] = pack_bf16(h0, h1);
                lp[p] = pack_bf16(l0, l1);
            }
            const int kc = j * 4 + quad;                      // 0..19
            const uint32_t off = (uint32_t)((e_loc * NCH + swzc(kc, e_loc)) * 16);
            *(uint4*)(smem + SM_A + off)            = hi4;
            *(uint4*)(smem + SM_A + SM_ALO_R + off) = lo4;
        }
    }
    __syncthreads();

    // --- GEMM: warp tile 16m x 32n, k = 160 in 10 steps of 16 ---------------
    const int wm = w & 7;                 // 0..7 : m0 = wm*16
    const int wn = w >> 3;                // 0..1 : n0 = wn*32
    const int m0 = wm * 16;
    const int n0 = wn * 32;

    // ldmatrix lane-address row/kc-offset components
    const int mrA  = m0 + ((l >> 3) & 1) * 8 + (l & 7);   // A: matrices m-low/m-high
    const int kselA = (l >> 4);                            // 0: k-low, 1: k-high
    const int nrB  = ((l >> 4) & 1) * 8 + (l & 7);        // B: n within 16-block
    const int kselB = ((l >> 3) & 1);

    float acc[4][4] = {{0.f}};
    #pragma unroll
    for (int ks = 0; ks < 10; ks++) {
        const int kc0 = ks * 2;
        uint32_t ah[4], al[4], bh0[4], bl0[4], bh1[4], bl1[4];
        {
            const int kc = kc0 + kselA;
            const uint32_t aoff = (uint32_t)((mrA * NCH + swzc(kc, mrA)) * 16);
            ldm_x4(ah, sbase + SM_A + aoff);
            ldm_x4(al, sbase + SM_A + SM_ALO_R + aoff);
        }
        {
            const int kc = kc0 + kselB;
            const int r0 = n0 + nrB;            // n-blocks 0,1
            const int r1 = n0 + 16 + nrB;       // n-blocks 2,3
            const uint32_t b0off = (uint32_t)((r0 * NCH + swzc(kc, r0)) * 16);
            const uint32_t b1off = (uint32_t)((r1 * NCH + swzc(kc, r1)) * 16);
            ldm_x4(bh0, sbase + SM_BHI + b0off);
            ldm_x4(bl0, sbase + SM_BLO + b0off);
            ldm_x4(bh1, sbase + SM_BHI + b1off);
            ldm_x4(bl1, sbase + SM_BLO + b1off);
        }
        // nblock 0: bh0[0..1], nblock 1: bh0[2..3], nblock 2: bh1[0..1], nblock3: bh1[2..3]
        mma16816(acc[0], ah, bh0);     mma16816(acc[1], ah, bh0 + 2);
        mma16816(acc[2], ah, bh1);     mma16816(acc[3], ah, bh1 + 2);
        mma16816(acc[0], ah, bl0);     mma16816(acc[1], ah, bl0 + 2);
        mma16816(acc[2], ah, bl1);     mma16816(acc[3], ah, bl1 + 2);
        mma16816(acc[0], al, bh0);     mma16816(acc[1], al, bh0 + 2);
        mma16816(acc[2], al, bh1);     mma16816(acc[3], al, bh1 + 2);
    }

    // --- epilogue: bias + stores (fragment layout -> out[b][o][e]) ----------
    {
        const int r  = m0 + (l >> 2);           // rows r, r+8
        const int e1 = e_base + r;
        const int e2 = e1 + 8;
        const bool ok1 = (e1 < E_);
        const bool ok2 = (e2 < E_);
        #pragma unroll
        for (int nb = 0; nb < 4; nb++) {
            const int n = n0 + nb * 8 + (l & 3) * 2;
            const float bn0 = __ldg(&bias[n]);
            const float bn1 = __ldg(&bias[n + 1]);
            float* o0 = out + ((size_t)(b * C_OUT_ + n)) * E_;
            float* o1 = out + ((size_t)(b * C_OUT_ + n + 1)) * E_;
            if (ok1) {
                o0[e1] = acc[nb][0] + bn0;
                o1[e1] = acc[nb][1] + bn1;
            }
            if (ok2) {
                o0[e2] = acc[nb][2] + bn0;
                o1[e2] = acc[nb][3] + bn1;
            }
        }
    }
}

// ---------------------------------------------------------------------------
extern "C" void kernel_launch(void* const* d_in, const int* in_sizes, int n_in,
                              void* d_out, int out_size) {
    const float* x    = (const float*)d_in[0];
    const int*   Gi   = (const int*)  d_in[1];
    const float* W    = (const float*)d_in[2];
    const float* bias = (const float*)d_in[3];
    float*       out  = (float*)d_out;

    transpose_x<<<dim3(E_ / 32, B_), 256>>>(x);
    prep_W<<<1, 512>>>(W);

    cudaFuncSetAttribute(meshconv_kernel,
                         cudaFuncAttributeMaxDynamicSharedMemorySize, SM_TOTAL);
    meshconv_kernel<<<dim3(N_TILES, B_), NTHR, SM_TOTAL>>>(Gi, bias, out);
}

// round 6
// speedup vs baseline: 4.1019x; 1.4385x over previous
#include <cuda_runtime.h>
#include <cuda_bf16.h>
#include <cstdint>

// Problem constants
#define B_      4
#define C_IN_   32
#define C_OUT_  64
#define E_      200000
#define KK_     5
#define CKDIM   160
#define TILE_M  128
#define NTHR    512
#define NCH     20             // 16B chunks per row (160 bf16 k-values)

#define TILES_PER_B  1563      // ceil(200000/128)
#define TOTAL_TILES  (B_ * TILES_PER_B)   // 6252
#define NCTA         148

// SMEM byte offsets
#define SM_BHI   0             // 64 x 320B
#define SM_BLO   20480
#define SM_A     40960         // Ahi 40960 | Alo 40960
#define SM_ALO_R 40960
#define SM_RAW   122880        // 640 lines x 128B = 81920
#define SM_CTRL  204800        // s_next tile index
#define SM_TOTAL 204816

// Global scratch
__device__ __align__(128) float g_xT[(size_t)B_ * E_ * C_IN_];   // (B,E,C)
__device__ __align__(128) unsigned char g_Bsplit[40960];         // Bhi | Blo panels
__device__ int g_ctr;

// ---------------------------------------------------------------------------
// helpers
// ---------------------------------------------------------------------------
__device__ __forceinline__ uint32_t smem_u32(const void* p) {
    uint32_t a;
    asm("{ .reg .u64 t; cvta.to.shared.u64 t, %1; cvt.u32.u64 %0, t; }" : "=r"(a) : "l"(p));
    return a;
}
__device__ __forceinline__ int swzc(int kc, int row) {
    return (kc < 16) ? (kc ^ (row & 7)) : (16 + ((kc - 16) ^ (row & 3)));
}
__device__ __forceinline__ void ldm_x4(uint32_t* r, uint32_t addr) {
    asm volatile("ldmatrix.sync.aligned.m8n8.x4.shared.b16 {%0,%1,%2,%3}, [%4];"
        : "=r"(r[0]), "=r"(r[1]), "=r"(r[2]), "=r"(r[3]) : "r"(addr));
}
__device__ __forceinline__ void mma16816(float* d, const uint32_t* a, const uint32_t* b) {
    asm volatile(
        "mma.sync.aligned.m16n8k16.row.col.f32.bf16.bf16.f32 "
        "{%0,%1,%2,%3}, {%4,%5,%6,%7}, {%8,%9}, {%0,%1,%2,%3};"
        : "+f"(d[0]), "+f"(d[1]), "+f"(d[2]), "+f"(d[3])
        : "r"(a[0]), "r"(a[1]), "r"(a[2]), "r"(a[3]), "r"(b[0]), "r"(b[1]));
}
// pack {lo=bf16(g0), hi=bf16(g1)}
__device__ __forceinline__ uint32_t cvt_bf16x2(float g0, float g1) {
    uint32_t r;
    asm("cvt.rn.bf16x2.f32 %0, %1, %2;" : "=r"(r) : "f"(g1), "f"(g0));
    return r;
}
__device__ __forceinline__ void cp_async16(uint32_t smem_addr, const void* gptr) {
    asm volatile("cp.async.cg.shared.global [%0], [%1], 16;"
                 :: "r"(smem_addr), "l"(gptr) : "memory");
}

// ---------------------------------------------------------------------------
// Kernel 1: transpose x (B,C,E) -> g_xT (B,E,C)
// ---------------------------------------------------------------------------
__global__ void __launch_bounds__(256) transpose_x(const float* __restrict__ x) {
    __shared__ float tile[32][33];
    const int b  = blockIdx.y;
    const int e0 = blockIdx.x * 32;
    const int tx = threadIdx.x & 31;
    const int ty = threadIdx.x >> 5;
    #pragma unroll
    for (int i = 0; i < 4; i++) {
        const int c = ty + i * 8;
        tile[c][tx] = x[((size_t)b * C_IN_ + c) * E_ + e0 + tx];
    }
    __syncthreads();
    #pragma unroll
    for (int i = 0; i < 4; i++) {
        const int e = ty + i * 8;
        g_xT[((size_t)b * E_ + e0 + e) * C_IN_ + tx] = tile[tx][e];
    }
}

// ---------------------------------------------------------------------------
// Kernel 2: split W into bf16 hi/lo, remap k = j*32 + c; also reset counter.
// ---------------------------------------------------------------------------
__global__ void __launch_bounds__(512) prep_W(const float* __restrict__ W) {
    if (threadIdx.x == 0) g_ctr = 0;
    for (int i = threadIdx.x; i < C_OUT_ * CKDIM; i += 512) {
        const int o   = i / CKDIM;
        const int rem = i - o * CKDIM;
        const int c   = rem / KK_;
        const int j   = rem - c * KK_;
        const int k   = j * 32 + c;
        const int kc  = k >> 3;
        const int ki  = k & 7;
        const float v = W[i];
        const __nv_bfloat16 hi = __float2bfloat16_rn(v);
        const __nv_bfloat16 lo = __float2bfloat16_rn(v - __bfloat162float(hi));
        const uint32_t off = (uint32_t)((o * NCH + swzc(kc, o)) * 16 + ki * 2);
        *reinterpret_cast<__nv_bfloat16*>(g_Bsplit + off)         = hi;
        *reinterpret_cast<__nv_bfloat16*>(g_Bsplit + 20480 + off) = lo;
    }
}

// ---------------------------------------------------------------------------
// device sub-routines for the persistent kernel
// ---------------------------------------------------------------------------
struct TileCtx {
    int b, e_base, valid;
};
__device__ __forceinline__ TileCtx decode_tile(int tile) {
    TileCtx tc;
    tc.b = tile / TILES_PER_B;
    const int r = tile - tc.b * TILES_PER_B;
    tc.e_base = r * TILE_M;
    tc.valid  = (E_ - tc.e_base) * KK_;     // >= 640 except last tile per batch
    return tc;
}

// load Gi lines for a tile into regs (10 per thread)
__device__ __forceinline__ void load_gi(int tile, int t, int gi[10]) {
    const TileCtx tc = decode_tile(tile);
    const int w = t >> 5, l = t & 31;
    const int sub = (l >> 3);
    const int* GiB = 0;
    // note: Gi pointer passed via global constant below (set each call site)
    (void)GiB;
    (void)tc; (void)w; (void)sub; (void)gi;
}

// ---------------------------------------------------------------------------
// Kernel 3: persistent fused gather(cp.async) + combine + HMMA + epilogue.
// ---------------------------------------------------------------------------
__global__ void __launch_bounds__(NTHR, 1)
meshconv_kernel(const int*   __restrict__ Gi,
                const float* __restrict__ bias,
                float*       __restrict__ out) {
    extern __shared__ __align__(1024) unsigned char smem[];
    const uint32_t sbase = smem_u32(smem);
    int* s_next = (int*)(smem + SM_CTRL);

    const int t   = threadIdx.x;
    const int w   = t >> 5;
    const int l   = t & 31;
    const int sub = (l >> 3);      // 0..3
    const int seg = l & 7;         // 0..7

    // --- B panels once per CTA ----------------------------------------------
    {
        const uint4* src = (const uint4*)g_Bsplit;
        uint4* dst = (uint4*)smem;
        #pragma unroll
        for (int i = 0; i < 5; i++) dst[t + i * NTHR] = src[t + i * NTHR];
    }

    // --- helpers as lambdas --------------------------------------------------
    auto grab = [&](void) {
        if (t == 0) *s_next = atomicAdd(&g_ctr, 1);
    };
    auto gi_load = [&](int tile, int gi[10]) {
        const TileCtx tc = decode_tile(tile);
        const int* GiB = Gi + (size_t)tc.b * E_ * KK_ + (size_t)tc.e_base * KK_;
        #pragma unroll
        for (int i = 0; i < 10; i++) {
            const int line = (w * 4 + sub) + i * 64;
            gi[i] = (line < tc.valid) ? GiB[line] : 0;
        }
    };
    auto gather_issue = [&](int tile, const int gi[10]) {
        const TileCtx tc = decode_tile(tile);
        const float* xb = g_xT + (size_t)tc.b * E_ * C_IN_;
        #pragma unroll
        for (int i = 0; i < 10; i++) {
            const int line  = (w * 4 + sub) + i * 64;
            const int chunk = seg ^ (line & 7);
            cp_async16(sbase + SM_RAW + (uint32_t)(line * 128 + chunk * 16),
                       xb + (size_t)gi[i] * C_IN_ + seg * 4);
        }
        asm volatile("cp.async.commit_group;" ::: "memory");
    };
    auto combine = [&](void) {
        const float4* sRaw4 = (const float4*)(smem + SM_RAW);
        const int e_loc = t >> 2;          // 0..127
        const int quad  = t & 3;
        float f[KK_][8];
        #pragma unroll
        for (int j = 0; j < KK_; j++) {
            const int row = e_loc * KK_ + j;
            #pragma unroll
            for (int q = 0; q < 2; q++) {
                const int chunk = (quad * 2 + q) ^ (row & 7);
                const float4 tmp = sRaw4[row * 8 + chunk];
                f[j][q * 4 + 0] = tmp.x; f[j][q * 4 + 1] = tmp.y;
                f[j][q * 4 + 2] = tmp.z; f[j][q * 4 + 3] = tmp.w;
            }
        }
        #pragma unroll
        for (int j = 0; j < KK_; j++) {
            float g[8];
            #pragma unroll
            for (int ci = 0; ci < 8; ci++) {
                const float f0 = f[0][ci], f1 = f[1][ci], f2 = f[2][ci],
                            f3 = f[3][ci], f4 = f[4][ci];
                switch (j) {
                    case 0: g[ci] = f0; break;
                    case 1: g[ci] = f1 + f3; break;
                    case 2: g[ci] = f2 + f4; break;
                    case 3: g[ci] = fabsf(f1 - f3); break;
                    default: g[ci] = fabsf(f2 - f4); break;
                }
            }
            uint4 hi4, lo4;
            uint32_t* hp = (uint32_t*)&hi4;
            uint32_t* lp = (uint32_t*)&lo4;
            #pragma unroll
            for (int p = 0; p < 4; p++) {
                const float g0 = g[2 * p], g1 = g[2 * p + 1];
                const uint32_t h = cvt_bf16x2(g0, g1);
                const float fh0 = __uint_as_float(h << 16);
                const float fh1 = __uint_as_float(h & 0xFFFF0000u);
                hp[p] = h;
                lp[p] = cvt_bf16x2(g0 - fh0, g1 - fh1);
            }
            const int kc = j * 4 + quad;
            const uint32_t off = (uint32_t)((e_loc * NCH + swzc(kc, e_loc)) * 16);
            *(uint4*)(smem + SM_A + off)            = hi4;
            *(uint4*)(smem + SM_A + SM_ALO_R + off) = lo4;
        }
    };

    // GEMM fragment geometry
    const int wm = w & 7, wn = w >> 3;
    const int m0 = wm * 16, n0 = wn * 32;
    const int mrA   = m0 + ((l >> 3) & 1) * 8 + (l & 7);
    const int kselA = (l >> 4);
    const int nrB   = ((l >> 4) & 1) * 8 + (l & 7);
    const int kselB = ((l >> 3) & 1);

    auto gemm_epilogue = [&](int tile) {
        float acc[4][4] = {{0.f}};
        #pragma unroll
        for (int ks = 0; ks < 10; ks++) {
            const int kc0 = ks * 2;
            uint32_t ah[4], al[4], bh0[4], bl0[4], bh1[4], bl1[4];
            {
                const int kc = kc0 + kselA;
                const uint32_t aoff = (uint32_t)((mrA * NCH + swzc(kc, mrA)) * 16);
                ldm_x4(ah, sbase + SM_A + aoff);
                ldm_x4(al, sbase + SM_A + SM_ALO_R + aoff);
            }
            {
                const int kc = kc0 + kselB;
                const int r0 = n0 + nrB;
                const int r1 = n0 + 16 + nrB;
                const uint32_t b0off = (uint32_t)((r0 * NCH + swzc(kc, r0)) * 16);
                const uint32_t b1off = (uint32_t)((r1 * NCH + swzc(kc, r1)) * 16);
                ldm_x4(bh0, sbase + SM_BHI + b0off);
                ldm_x4(bl0, sbase + SM_BLO + b0off);
                ldm_x4(bh1, sbase + SM_BHI + b1off);
                ldm_x4(bl1, sbase + SM_BLO + b1off);
            }
            mma16816(acc[0], ah, bh0);     mma16816(acc[1], ah, bh0 + 2);
            mma16816(acc[2], ah, bh1);     mma16816(acc[3], ah, bh1 + 2);
            mma16816(acc[0], ah, bl0);     mma16816(acc[1], ah, bl0 + 2);
            mma16816(acc[2], ah, bl1);     mma16816(acc[3], ah, bl1 + 2);
            mma16816(acc[0], al, bh0);     mma16816(acc[1], al, bh0 + 2);
            mma16816(acc[2], al, bh1);     mma16816(acc[3], al, bh1 + 2);
        }
        const TileCtx tc = decode_tile(tile);
        const int r  = m0 + (l >> 2);
        const int e1 = tc.e_base + r;
        const int e2 = e1 + 8;
        const bool ok1 = (e1 < E_);
        const bool ok2 = (e2 < E_);
        #pragma unroll
        for (int nb = 0; nb < 4; nb++) {
            const int n = n0 + nb * 8 + (l & 3) * 2;
            const float bn0 = __ldg(&bias[n]);
            const float bn1 = __ldg(&bias[n + 1]);
            float* o0 = out + ((size_t)(tc.b * C_OUT_ + n)) * E_;
            float* o1 = out + ((size_t)(tc.b * C_OUT_ + n + 1)) * E_;
            if (ok1) { o0[e1] = acc[nb][0] + bn0; o1[e1] = acc[nb][1] + bn1; }
            if (ok2) { o0[e2] = acc[nb][2] + bn0; o1[e2] = acc[nb][3] + bn1; }
        }
    };

    // --- prologue: first tile ------------------------------------------------
    grab();
    __syncthreads();
    int cur = *s_next;
    if (cur >= TOTAL_TILES) return;

    int gi[10];
    gi_load(cur, gi);
    gather_issue(cur, gi);
    asm volatile("cp.async.wait_group 0;" ::: "memory");
    grab();                        // fetch 'nxt' index while waiting
    __syncthreads();
    int nxt = *s_next;
    combine();                     // raw -> A panels (tile cur)
    if (nxt < TOTAL_TILES) gi_load(nxt, gi);
    __syncthreads();

    // --- main pipelined loop -------------------------------------------------
    for (;;) {
        if (nxt < TOTAL_TILES) gather_issue(nxt, gi);   // overlap with GEMM
        grab();                                          // prefetch next-next idx
        gemm_epilogue(cur);
        if (nxt >= TOTAL_TILES) break;
        asm volatile("cp.async.wait_group 0;" ::: "memory");
        __syncthreads();                                 // raw ready; s_next visible
        const int nnxt = *s_next;
        if (nnxt < TOTAL_TILES) gi_load(nnxt, gi);       // LDG overlaps combine
        combine();                                       // raw -> A (tile nxt)
        __syncthreads();                                 // A ready for next GEMM
        cur = nxt;
        nxt = nnxt;
    }
}

// ---------------------------------------------------------------------------
extern "C" void kernel_launch(void* const* d_in, const int* in_sizes, int n_in,
                              void* d_out, int out_size) {
    const float* x    = (const float*)d_in[0];
    const int*   Gi   = (const int*)  d_in[1];
    const float* W    = (const float*)d_in[2];
    const float* bias = (const float*)d_in[3];
    float*       out  = (float*)d_out;

    transpose_x<<<dim3(E_ / 32, B_), 256>>>(x);
    prep_W<<<1, 512>>>(W);

    cudaFuncSetAttribute(meshconv_kernel,
                         cudaFuncAttributeMaxDynamicSharedMemorySize, SM_TOTAL);
    meshconv_kernel<<<NCTA, NTHR, SM_TOTAL>>>(Gi, bias, out);
}

// round 8
// speedup vs baseline: 4.4089x; 1.0749x over previous
#include <cuda_runtime.h>
#include <cuda_fp16.h>
#include <cstdint>

// Problem constants
#define B_      4
#define C_IN_   32
#define C_OUT_  64
#define E_      200000
#define KK_     5
#define CKDIM   160
#define TILE_M  128
#define NTHR    512
#define NCH     20             // 16B chunks per row (160 fp16 k-values)

#define TILES_PER_B  1563
#define TOTAL_TILES  (B_ * TILES_PER_B)   // 6252
#define NCTA         148

// SMEM byte offsets
#define SM_BH    0             // W fp16 panel: 64 x 320B = 20480
#define SM_A     20480         // A fp16 panel: 128 x 320B = 40960
#define SM_RAW   61440         // 640 lines x 128B = 81920
#define SM_OUT   143360        // 64 x 132 x 4B = 33792 (epilogue staging)
#define SM_CTRL  177152
#define SM_TOTAL 177168

#define OUT_PITCH 132          // floats per o-row in staging (conflict-free)

// Global scratch
__device__ __align__(128) float g_xT[(size_t)B_ * E_ * C_IN_];   // (B,E,C)
__device__ __align__(128) unsigned char g_Bh[20480];             // W fp16 panel
__device__ int g_ctr;

// ---------------------------------------------------------------------------
// helpers
// ---------------------------------------------------------------------------
__device__ __forceinline__ uint32_t smem_u32(const void* p) {
    uint32_t a;
    asm("{ .reg .u64 t; cvta.to.shared.u64 t, %1; cvt.u32.u64 %0, t; }" : "=r"(a) : "l"(p));
    return a;
}
__device__ __forceinline__ int swzc(int kc, int row) {
    return (kc < 16) ? (kc ^ (row & 7)) : (16 + ((kc - 16) ^ (row & 3)));
}
__device__ __forceinline__ void ldm_x4(uint32_t* r, uint32_t addr) {
    asm volatile("ldmatrix.sync.aligned.m8n8.x4.shared.b16 {%0,%1,%2,%3}, [%4];"
        : "=r"(r[0]), "=r"(r[1]), "=r"(r[2]), "=r"(r[3]) : "r"(addr));
}
__device__ __forceinline__ void mma16816(float* d, const uint32_t* a, const uint32_t* b) {
    asm volatile(
        "mma.sync.aligned.m16n8k16.row.col.f32.f16.f16.f32 "
        "{%0,%1,%2,%3}, {%4,%5,%6,%7}, {%8,%9}, {%0,%1,%2,%3};"
        : "+f"(d[0]), "+f"(d[1]), "+f"(d[2]), "+f"(d[3])
        : "r"(a[0]), "r"(a[1]), "r"(a[2]), "r"(a[3]), "r"(b[0]), "r"(b[1]));
}
__device__ __forceinline__ uint32_t pack_half2(float g0, float g1) {
    __half2 h = __floats2half2_rn(g0, g1);   // x = g0 (low), y = g1 (high)
    return *reinterpret_cast<uint32_t*>(&h);
}
__device__ __forceinline__ void cp_async16(uint32_t smem_addr, const void* gptr) {
    asm volatile("cp.async.cg.shared.global [%0], [%1], 16;"
                 :: "r"(smem_addr), "l"(gptr) : "memory");
}

// ---------------------------------------------------------------------------
// Kernel 1: transpose x (B,C,E) -> g_xT (B,E,C)
// ---------------------------------------------------------------------------
__global__ void __launch_bounds__(256) transpose_x(const float* __restrict__ x) {
    __shared__ float tile[32][33];
    const int b  = blockIdx.y;
    const int e0 = blockIdx.x * 32;
    const int tx = threadIdx.x & 31;
    const int ty = threadIdx.x >> 5;
    #pragma unroll
    for (int i = 0; i < 4; i++) {
        const int c = ty + i * 8;
        tile[c][tx] = x[((size_t)b * C_IN_ + c) * E_ + e0 + tx];
    }
    __syncthreads();
    #pragma unroll
    for (int i = 0; i < 4; i++) {
        const int e = ty + i * 8;
        g_xT[((size_t)b * E_ + e0 + e) * C_IN_ + tx] = tile[tx][e];
    }
}

// ---------------------------------------------------------------------------
// Kernel 2: W -> fp16 panel, remap k = j*32 + c; reset tile counter.
// ---------------------------------------------------------------------------
__global__ void __launch_bounds__(512) prep_W(const float* __restrict__ W) {
    if (threadIdx.x == 0) g_ctr = 0;
    for (int i = threadIdx.x; i < C_OUT_ * CKDIM; i += 512) {
        const int o   = i / CKDIM;
        const int rem = i - o * CKDIM;
        const int c   = rem / KK_;
        const int j   = rem - c * KK_;
        const int k   = j * 32 + c;
        const int kc  = k >> 3;
        const int ki  = k & 7;
        const uint32_t off = (uint32_t)((o * NCH + swzc(kc, o)) * 16 + ki * 2);
        *reinterpret_cast<__half*>(g_Bh + off) = __float2half_rn(W[i]);
    }
}

// ---------------------------------------------------------------------------
struct TileCtx { int b, e_base, valid; };
__device__ __forceinline__ TileCtx decode_tile(int tile) {
    TileCtx tc;
    tc.b = tile / TILES_PER_B;
    const int r = tile - tc.b * TILES_PER_B;
    tc.e_base = r * TILE_M;
    tc.valid  = (E_ - tc.e_base) * KK_;
    return tc;
}

// ---------------------------------------------------------------------------
// Kernel 3: persistent fused gather(cp.async) + combine + fp16 HMMA + epilogue
// ---------------------------------------------------------------------------
__global__ void __launch_bounds__(NTHR, 1)
meshconv_kernel(const int*   __restrict__ Gi,
                const float* __restrict__ bias,
                float*       __restrict__ out) {
    extern __shared__ __align__(1024) unsigned char smem[];
    const uint32_t sbase = smem_u32(smem);
    int* s_next = (int*)(smem + SM_CTRL);
    float* s_out = (float*)(smem + SM_OUT);

    const int t   = threadIdx.x;
    const int w   = t >> 5;
    const int l   = t & 31;
    const int sub = (l >> 3);
    const int seg = l & 7;

    // --- W panel once per CTA (20KB, coalesced) -----------------------------
    {
        const uint4* src = (const uint4*)g_Bh;
        uint4* dst = (uint4*)smem;
        #pragma unroll
        for (int i = 0; i < 3; i++) {
            const int idx = t + i * NTHR;
            if (idx < 1280) dst[idx] = src[idx];
        }
    }

    auto grab = [&](void) {
        if (t == 0) *s_next = atomicAdd(&g_ctr, 1);
    };
    auto gi_load = [&](int tile, int gi[10]) {
        const TileCtx tc = decode_tile(tile);
        const int* GiB = Gi + (size_t)tc.b * E_ * KK_ + (size_t)tc.e_base * KK_;
        #pragma unroll
        for (int i = 0; i < 10; i++) {
            const int line = (w * 4 + sub) + i * 64;
            gi[i] = (line < tc.valid) ? GiB[line] : 0;
        }
    };
    auto gather_issue = [&](int tile, const int gi[10]) {
        const TileCtx tc = decode_tile(tile);
        const float* xb = g_xT + (size_t)tc.b * E_ * C_IN_;
        #pragma unroll
        for (int i = 0; i < 10; i++) {
            const int line  = (w * 4 + sub) + i * 64;
            const int chunk = seg ^ (line & 7);
            cp_async16(sbase + SM_RAW + (uint32_t)(line * 128 + chunk * 16),
                       xb + (size_t)gi[i] * C_IN_ + seg * 4);
        }
        asm volatile("cp.async.commit_group;" ::: "memory");
    };
    auto combine = [&](void) {
        const float4* sRaw4 = (const float4*)(smem + SM_RAW);
        const int e_loc = t >> 2;
        const int quad  = t & 3;
        float f[KK_][8];
        #pragma unroll
        for (int j = 0; j < KK_; j++) {
            const int row = e_loc * KK_ + j;
            #pragma unroll
            for (int q = 0; q < 2; q++) {
                const int chunk = (quad * 2 + q) ^ (row & 7);
                const float4 tmp = sRaw4[row * 8 + chunk];
                f[j][q * 4 + 0] = tmp.x; f[j][q * 4 + 1] = tmp.y;
                f[j][q * 4 + 2] = tmp.z; f[j][q * 4 + 3] = tmp.w;
            }
        }
        #pragma unroll
        for (int j = 0; j < KK_; j++) {
            float g[8];
            #pragma unroll
            for (int ci = 0; ci < 8; ci++) {
                const float f0 = f[0][ci], f1 = f[1][ci], f2 = f[2][ci],
                            f3 = f[3][ci], f4 = f[4][ci];
                switch (j) {
                    case 0: g[ci] = f0; break;
                    case 1: g[ci] = f1 + f3; break;
                    case 2: g[ci] = f2 + f4; break;
                    case 3: g[ci] = fabsf(f1 - f3); break;
                    default: g[ci] = fabsf(f2 - f4); break;
                }
            }
            uint4 h4;
            uint32_t* hp = (uint32_t*)&h4;
            #pragma unroll
            for (int p = 0; p < 4; p++) hp[p] = pack_half2(g[2 * p], g[2 * p + 1]);
            const int kc = j * 4 + quad;
            const uint32_t off = (uint32_t)((e_loc * NCH + swzc(kc, e_loc)) * 16);
            *(uint4*)(smem + SM_A + off) = h4;
        }
    };

    // GEMM fragment geometry: 16 warps = 8m x 2n, warp tile 16m x 32n
    const int wm = w & 7, wn = w >> 3;
    const int m0 = wm * 16, n0 = wn * 32;
    const int mrA   = m0 + ((l >> 3) & 1) * 8 + (l & 7);
    const int kselA = (l >> 4);
    const int nrB   = ((l >> 4) & 1) * 8 + (l & 7);
    const int kselB = ((l >> 3) & 1);

    auto gemm_epilogue = [&](int tile) {
        float acc[4][4] = {{0.f}};
        #pragma unroll
        for (int ks = 0; ks < 10; ks++) {
            const int kc0 = ks * 2;
            uint32_t a4[4], b0[4], b1[4];
            {
                const int kc = kc0 + kselA;
                const uint32_t aoff = (uint32_t)((mrA * NCH + swzc(kc, mrA)) * 16);
                ldm_x4(a4, sbase + SM_A + aoff);
            }
            {
                const int kc = kc0 + kselB;
                const int r0 = n0 + nrB;
                const int r1 = n0 + 16 + nrB;
                ldm_x4(b0, sbase + SM_BH + (uint32_t)((r0 * NCH + swzc(kc, r0)) * 16));
                ldm_x4(b1, sbase + SM_BH + (uint32_t)((r1 * NCH + swzc(kc, r1)) * 16));
            }
            mma16816(acc[0], a4, b0);     mma16816(acc[1], a4, b0 + 2);
            mma16816(acc[2], a4, b1);     mma16816(acc[3], a4, b1 + 2);
        }
        // --- stage accumulators (+bias) into s_out[o][e], conflict-free -----
        const TileCtx tc = decode_tile(tile);
        const int r = m0 + (l >> 2);
        #pragma unroll
        for (int nb = 0; nb < 4; nb++) {
            const int n = n0 + nb * 8 + (l & 3) * 2;
            const float bn0 = __ldg(&bias[n]);
            const float bn1 = __ldg(&bias[n + 1]);
            s_out[n * OUT_PITCH + r]           = acc[nb][0] + bn0;
            s_out[(n + 1) * OUT_PITCH + r]     = acc[nb][1] + bn1;
            s_out[n * OUT_PITCH + r + 8]       = acc[nb][2] + bn0;
            s_out[(n + 1) * OUT_PITCH + r + 8] = acc[nb][3] + bn1;
        }
        __syncthreads();
        // --- coalesced float4 stores: thread -> (o = t>>3, e-chunk = t&7) ---
        {
            const int o     = t >> 3;
            const int chunk = t & 7;
            const int valid_e = E_ - tc.e_base;            // 128 or 64
            if (chunk * 16 < valid_e) {
                float* orow = out + ((size_t)(tc.b * C_OUT_ + o)) * E_ + tc.e_base;
                const float* srow = s_out + o * OUT_PITCH + chunk * 16;
                #pragma unroll
                for (int i = 0; i < 4; i++) {
                    float4 v = make_float4(srow[i * 4 + 0], srow[i * 4 + 1],
                                           srow[i * 4 + 2], srow[i * 4 + 3]);
                    *(float4*)(orow + chunk * 16 + i * 4) = v;
                }
            }
        }
    };

    // --- prologue ------------------------------------------------------------
    grab();
    __syncthreads();
    int cur = *s_next;
    if (cur >= TOTAL_TILES) return;

    int gi[10];
    gi_load(cur, gi);
    gather_issue(cur, gi);
    asm volatile("cp.async.wait_group 0;" ::: "memory");
    grab();
    __syncthreads();
    int nxt = *s_next;
    combine();
    if (nxt < TOTAL_TILES) gi_load(nxt, gi);
    __syncthreads();

    // --- main pipelined loop -------------------------------------------------
    for (;;) {
        if (nxt < TOTAL_TILES) gather_issue(nxt, gi);   // overlaps GEMM below
        grab();
        gemm_epilogue(cur);                             // contains one sync
        if (nxt >= TOTAL_TILES) break;
        asm volatile("cp.async.wait_group 0;" ::: "memory");
        __syncthreads();                                // raw + staged reads done
        const int nnxt = *s_next;
        if (nnxt < TOTAL_TILES) gi_load(nnxt, gi);
        combine();
        __syncthreads();                                // A panel ready
        cur = nxt;
        nxt = nnxt;
    }
}

// ---------------------------------------------------------------------------
extern "C" void kernel_launch(void* const* d_in, const int* in_sizes, int n_in,
                              void* d_out, int out_size) {
    const float* x    = (const float*)d_in[0];
    const int*   Gi   = (const int*)  d_in[1];
    const float* W    = (const float*)d_in[2];
    const float* bias = (const float*)d_in[3];
    float*       out  = (float*)d_out;

    transpose_x<<<dim3(E_ / 32, B_), 256>>>(x);
    prep_W<<<1, 512>>>(W);

    cudaFuncSetAttribute(meshconv_kernel,
                         cudaFuncAttributeMaxDynamicSharedMemorySize, SM_TOTAL);
    meshconv_kernel<<<NCTA, NTHR, SM_TOTAL>>>(Gi, bias, out);
}